// round 15
// baseline (speedup 1.0000x reference)
#include <cuda_runtime.h>
#include <cuda_fp16.h>
#include <math.h>
#include <stdint.h>

#define BSZ 4
#define SEQ 2048
#define EMB 1024
#define NQKV 3072

// ---------------------------------------------------------------------------
// Scratch (__device__ globals: no allocations allowed)
// ---------------------------------------------------------------------------
__device__ __align__(16) __half g_xr [(size_t)BSZ * SEQ * EMB];     // x -> fp16
__device__ __align__(16) __half g_qkv[(size_t)BSZ * SEQ * NQKV];    // q|k|v interleaved
__device__ __align__(16) __half g_s  [(size_t)BSZ * SEQ * SEQ];     // E = exp(scores)
__device__ __align__(16) __half g_wt [3 * (size_t)EMB * EMB];       // W^T fp16 (q|k|v)
__device__ __align__(16) __half g_vt [(size_t)BSZ * EMB * SEQ];     // V^T / colsum
__device__ float g_csp[16 * (size_t)BSZ * SEQ];  // colsum partials (per m-tile)
__device__ float g_bc [NQKV];                    // concatenated bias

// ---------------------------------------------------------------------------
// Helpers
// ---------------------------------------------------------------------------
__device__ __forceinline__ uint32_t smem_u32(const void* p) {
    uint32_t a;
    asm("{ .reg .u64 t; cvta.to.shared.u64 t, %1; cvt.u32.u64 %0, t; }" : "=r"(a) : "l"(p));
    return a;
}
__device__ __forceinline__ void cpa16(uint32_t dst, const void* src) {
    asm volatile("cp.async.cg.shared.global [%0], [%1], 16;" :: "r"(dst), "l"(src));
}
#define CP_COMMIT() asm volatile("cp.async.commit_group;" ::: "memory")
#define CP_WAIT1()  asm volatile("cp.async.wait_group 1;" ::: "memory")

__device__ __forceinline__ void mma_f16(float* c,
    uint32_t a0, uint32_t a1, uint32_t a2, uint32_t a3, uint32_t b0, uint32_t b1)
{
    asm volatile("mma.sync.aligned.m16n8k16.row.col.f32.f16.f16.f32 "
        "{%0,%1,%2,%3}, {%4,%5,%6,%7}, {%8,%9}, {%0,%1,%2,%3};"
        : "+f"(c[0]), "+f"(c[1]), "+f"(c[2]), "+f"(c[3])
        : "r"(a0), "r"(a1), "r"(a2), "r"(a3), "r"(b0), "r"(b1));
}
__device__ __forceinline__ void ldsm_x4(uint32_t& r0, uint32_t& r1,
                                        uint32_t& r2, uint32_t& r3, uint32_t addr)
{
    asm volatile("ldmatrix.sync.aligned.m8n8.x4.shared.b16 {%0,%1,%2,%3}, [%4];"
        : "=r"(r0), "=r"(r1), "=r"(r2), "=r"(r3) : "r"(addr));
}

// ---------------------------------------------------------------------------
// fp16 mma.sync GEMM, NT: C[m][n] = epi(alpha * sum_k A[m][k]*B[n][k])
// 128x64x64 CTA tile (halves), 128 threads (4 warps of 64x32 -- identical
// per-warp fragment/HMMA code to the 256-thread 128x128 version), 3-stage
// cp.async, ldmatrix operand loads. Small tiles -> fine-grained CTA scheduling
// (many CTAs per SM) -> wave-quantization tail shrinks from ~15% to ~2-7%.
// lda/ldb/ldc are row strides in elements; K is the contraction length.
// EPI_EXP also emits deterministic per-CTA column partial sums to csp.
// ---------------------------------------------------------------------------
#define BM 128
#define BN 64
#define BKH 64                        // halves per k-tile (128 bytes/row)
#define STAGES 3
#define PADW 36                       // b32 words per smem row (32 data + 4 pad)
#define ROW_BYTES (PADW * 4)          // 144
#define A_BYTES (BM * ROW_BYTES)      // 18432
#define B_BYTES (BN * ROW_BYTES)      // 9216
#define STAGE_BYTES (A_BYTES + B_BYTES)     // 27648
#define SMEM_BYTES (STAGES * STAGE_BYTES)   // 82944

#define EPI_BIAS 0
#define EPI_EXP  1
#define EPI_NONE 2

template <int EPI, typename OutT>
__global__ void __launch_bounds__(128, 2) hmma_gemm_nt(
    const __half* __restrict__ A, const __half* __restrict__ B,
    const float* __restrict__ bias, OutT* __restrict__ C,
    float* __restrict__ csp,
    int K, int lda, int ldb, int ldc, float alpha,
    size_t sA, size_t sB, size_t sC)
{
    extern __shared__ char smem[];
    A += (size_t)blockIdx.z * sA;
    B += (size_t)blockIdx.z * sB;
    C += (size_t)blockIdx.z * sC;

    const int tid  = threadIdx.x;
    const int lane = tid & 31;
    const int wid  = tid >> 5;        // 0..3
    const int wm   = wid & 1;         // 2 m-slices of 64
    const int wn   = wid >> 1;        // 2 n-slices of 32
    const int bm = blockIdx.y * BM;
    const int bn = blockIdx.x * BN;

    const __half* Ab = A + (size_t)bm * lda;
    const __half* Bb = B + (size_t)bn * ldb;
    const uint32_t sb = smem_u32(smem);

    const int NT = K >> 6;            // k-tiles of 64 halves
    const int lr = tid >> 3;          // 0..15 base row
    const int lc = tid & 7;           // 16B chunk in 128B row

    // ldmatrix per-thread base offsets (within a stage)
    uint32_t a_off[4];
    #pragma unroll
    for (int mf = 0; mf < 4; mf++)
        a_off[mf] = (uint32_t)(wm * 64 + mf * 16 + (lane & 15)) * ROW_BYTES
                  + (uint32_t)(lane >> 4) * 16;
    uint32_t b_off[2];
    #pragma unroll
    for (int p = 0; p < 2; p++)
        b_off[p] = A_BYTES
                 + (uint32_t)(wn * 32 + p * 16 + (lane & 7) + ((lane >> 4) & 1) * 8) * ROW_BYTES
                 + (uint32_t)((lane >> 3) & 1) * 16;

    // prologue: stages 0..1
    #pragma unroll
    for (int st = 0; st < STAGES - 1; st++) {
        const int k0 = st * BKH;
        const uint32_t dA = sb + (uint32_t)st * STAGE_BYTES;
        const uint32_t dB = dA + A_BYTES;
        #pragma unroll
        for (int i = 0; i < 8; i++) {           // A: 128 rows
            const int m = lr + 16 * i;
            cpa16(dA + (uint32_t)m * ROW_BYTES + lc * 16, Ab + (size_t)m * lda + k0 + lc * 8);
        }
        #pragma unroll
        for (int i = 0; i < 4; i++) {           // B: 64 rows
            const int m = lr + 16 * i;
            cpa16(dB + (uint32_t)m * ROW_BYTES + lc * 16, Bb + (size_t)m * ldb + k0 + lc * 8);
        }
        CP_COMMIT();
    }

    float acc[64];
    #pragma unroll
    for (int i = 0; i < 64; i++) acc[i] = 0.0f;

    const int g  = lane >> 2;         // 0..7
    const int tg = lane & 3;          // 0..3

    for (int kt = 0; kt < NT; kt++) {
        CP_WAIT1();
        __syncthreads();

        if (kt + STAGES - 1 < NT) {
            const int st = (kt + STAGES - 1) % STAGES;
            const int k0 = (kt + STAGES - 1) * BKH;
            const uint32_t dA = sb + (uint32_t)st * STAGE_BYTES;
            const uint32_t dB = dA + A_BYTES;
            #pragma unroll
            for (int i = 0; i < 8; i++) {
                const int m = lr + 16 * i;
                cpa16(dA + (uint32_t)m * ROW_BYTES + lc * 16, Ab + (size_t)m * lda + k0 + lc * 8);
            }
            #pragma unroll
            for (int i = 0; i < 4; i++) {
                const int m = lr + 16 * i;
                cpa16(dB + (uint32_t)m * ROW_BYTES + lc * 16, Bb + (size_t)m * ldb + k0 + lc * 8);
            }
        }
        CP_COMMIT();

        const uint32_t stage = sb + (uint32_t)(kt % STAGES) * STAGE_BYTES;

        #pragma unroll
        for (int ch = 0; ch < 4; ch++) {          // 4 k16-chunks per tile
            const uint32_t cb = stage + ch * 32;  // 32B = 16 halves along k
            uint32_t a[4][4];
            #pragma unroll
            for (int mf = 0; mf < 4; mf++)
                ldsm_x4(a[mf][0], a[mf][1], a[mf][2], a[mf][3], cb + a_off[mf]);
            uint32_t b[2][4];
            #pragma unroll
            for (int p = 0; p < 2; p++)
                ldsm_x4(b[p][0], b[p][1], b[p][2], b[p][3], cb + b_off[p]);

            #pragma unroll
            for (int mf = 0; mf < 4; mf++) {
                #pragma unroll
                for (int nf = 0; nf < 4; nf++) {
                    const int p = nf >> 1, h = nf & 1;
                    mma_f16(&acc[(mf * 4 + nf) * 4],
                            a[mf][0], a[mf][1], a[mf][2], a[mf][3],
                            b[p][h * 2 + 0], b[p][h * 2 + 1]);
                }
            }
        }
    }

    // ---------------- Epilogue ----------------
    float psum[4][2];
    if (EPI == EPI_EXP) {
        #pragma unroll
        for (int nf = 0; nf < 4; nf++) { psum[nf][0] = 0.f; psum[nf][1] = 0.f; }
    }

    const int cc = tg * 2;
    #pragma unroll
    for (int mf = 0; mf < 4; mf++) {
        #pragma unroll
        for (int rh = 0; rh < 2; rh++) {
            const int row = bm + wm * 64 + mf * 16 + rh * 8 + g;
            OutT* crow = C + (size_t)row * ldc + bn + wn * 32;
            #pragma unroll
            for (int nf = 0; nf < 4; nf++) {
                float v0 = acc[(mf * 4 + nf) * 4 + rh * 2 + 0];
                float v1 = acc[(mf * 4 + nf) * 4 + rh * 2 + 1];
                const int col = nf * 8 + cc;
                if (EPI == EPI_BIAS) {
                    const __half h0 = __float2half_rn(v0 + bias[bn + wn * 32 + col + 0]);
                    const __half h1 = __float2half_rn(v1 + bias[bn + wn * 32 + col + 1]);
                    *(__half2*)((__half*)crow + col) = __halves2half2(h0, h1);
                } else if (EPI == EPI_EXP) {
                    const __half h0 = __float2half_rn(__expf(v0 * alpha));
                    const __half h1 = __float2half_rn(__expf(v1 * alpha));
                    psum[nf][0] += __half2float(h0);   // sum the EXACT stored values
                    psum[nf][1] += __half2float(h1);
                    *(__half2*)((__half*)crow + col) = __halves2half2(h0, h1);
                } else {
                    *(float2*)((float*)crow + col) = make_float2(v0, v1);
                }
            }
        }
    }

    if (EPI == EPI_EXP) {
        // reduce over g (lanes xor 4,8,16 share the same column pair)
        #pragma unroll
        for (int nf = 0; nf < 4; nf++) {
            #pragma unroll
            for (int h = 0; h < 2; h++) {
                float v = psum[nf][h];
                v += __shfl_xor_sync(0xffffffffu, v, 4);
                v += __shfl_xor_sync(0xffffffffu, v, 8);
                v += __shfl_xor_sync(0xffffffffu, v, 16);
                psum[nf][h] = v;
            }
        }
        __syncthreads();                      // mainloop smem reads done
        float* csum = (float*)smem;           // reuse: [2][64]
        if (g == 0) {
            #pragma unroll
            for (int nf = 0; nf < 4; nf++) {
                csum[wm * 64 + wn * 32 + nf * 8 + cc + 0] = psum[nf][0];
                csum[wm * 64 + wn * 32 + nf * 8 + cc + 1] = psum[nf][1];
            }
        }
        __syncthreads();
        if (tid < 64) {
            const float t = csum[tid] + csum[64 + tid];   // wm0 + wm1 (same order)
            csp[(size_t)blockIdx.y * BSZ * SEQ + (size_t)blockIdx.z * SEQ + bn + tid] = t;
        }
    }
}

// ---------------------------------------------------------------------------
// x -> fp16 copy
// ---------------------------------------------------------------------------
__global__ void f2h_kernel(const float4* __restrict__ in, __half2* __restrict__ out)
{
    const size_t i = (size_t)blockIdx.x * blockDim.x + threadIdx.x;
    const float4 v = in[i];
    out[2 * i + 0] = __floats2half2_rn(v.x, v.y);
    out[2 * i + 1] = __floats2half2_rn(v.z, v.w);
}

// ---------------------------------------------------------------------------
// Concatenate the three bias vectors -> [3072]
// ---------------------------------------------------------------------------
__global__ void bias_cat_kernel(const float* __restrict__ bq, const float* __restrict__ bk,
                                const float* __restrict__ bv, float* __restrict__ bc)
{
    const int i = blockIdx.x * 256 + threadIdx.x;
    bc[i]            = bq[i];
    bc[EMB + i]      = bk[i];
    bc[2 * EMB + i]  = bv[i];
}

// ---------------------------------------------------------------------------
// Merged weight transpose (grid.z selects W): wt[z][n][k] = (half)W_z[k][n]
// ---------------------------------------------------------------------------
__global__ void wtrans_kernel(const float* __restrict__ W0, const float* __restrict__ W1,
                              const float* __restrict__ W2, __half* __restrict__ wt)
{
    __shared__ float t[32][33];
    const int z = blockIdx.z;
    const float* in = (z == 0) ? W0 : (z == 1) ? W1 : W2;
    __half* out = wt + (size_t)z * EMB * EMB;
    const int r0 = blockIdx.y * 32, c0 = blockIdx.x * 32;
    #pragma unroll
    for (int i = threadIdx.y; i < 32; i += 8)
        t[i][threadIdx.x] = in[(size_t)(r0 + i) * EMB + c0 + threadIdx.x];
    __syncthreads();
    #pragma unroll
    for (int i = threadIdx.y; i < 32; i += 8)
        out[(size_t)(c0 + i) * EMB + r0 + threadIdx.x] = __float2half_rn(t[threadIdx.x][i]);
}

// ---------------------------------------------------------------------------
// Vt build with inline colsum combine:
//   cs[k] = sum_{c<16} csp[c][b][k]   (same order as before -> deterministic)
//   vt[e][k] = (half)( v[k][e] / cs[k] )      v = qkv column block 2048..3071
// ---------------------------------------------------------------------------
__global__ void vt_kernel(const __half* __restrict__ qkv, __half* __restrict__ vt,
                          const float* __restrict__ csp)
{
    __shared__ float t[32][33];
    __shared__ float inv[32];
    const int b = blockIdx.z;
    const __half* v = qkv + (size_t)b * SEQ * NQKV + 2 * EMB;
    __half* vo = vt + (size_t)b * EMB * SEQ;
    const int r0 = blockIdx.y * 32;   // k rows
    const int c0 = blockIdx.x * 32;   // e cols
    const int tid = threadIdx.y * 32 + threadIdx.x;

    if (tid < 32) {
        float s = 0.f;
        #pragma unroll
        for (int c = 0; c < 16; c++)
            s += csp[(size_t)c * BSZ * SEQ + (size_t)b * SEQ + r0 + tid];
        inv[tid] = __fdividef(1.0f, s);
    }
    __syncthreads();

    #pragma unroll
    for (int i = threadIdx.y; i < 32; i += 8)
        t[i][threadIdx.x] = __half2float(v[(size_t)(r0 + i) * NQKV + c0 + threadIdx.x]) * inv[i];
    __syncthreads();
    #pragma unroll
    for (int i = threadIdx.y; i < 32; i += 8)
        vo[(size_t)(c0 + i) * SEQ + r0 + threadIdx.x] = __float2half_rn(t[threadIdx.x][i]);
}

// ---------------------------------------------------------------------------
// Launch
// ---------------------------------------------------------------------------
extern "C" void kernel_launch(void* const* d_in, const int* in_sizes, int n_in,
                              void* d_out, int out_size)
{
    const float* x  = (const float*)d_in[0];
    const float* Wq = (const float*)d_in[1];
    const float* bq = (const float*)d_in[2];
    const float* Wk = (const float*)d_in[3];
    const float* bk = (const float*)d_in[4];
    const float* Wv = (const float*)d_in[5];
    const float* bv = (const float*)d_in[6];
    float* out = (float*)d_out;

    __half *xr, *qkv, *s, *wt, *vt;
    float *csp, *bc;
    cudaGetSymbolAddress((void**)&xr,  g_xr);
    cudaGetSymbolAddress((void**)&qkv, g_qkv);
    cudaGetSymbolAddress((void**)&s,   g_s);
    cudaGetSymbolAddress((void**)&wt,  g_wt);
    cudaGetSymbolAddress((void**)&vt,  g_vt);
    cudaGetSymbolAddress((void**)&csp, g_csp);
    cudaGetSymbolAddress((void**)&bc,  g_bc);

    cudaFuncSetAttribute((const void*)hmma_gemm_nt<EPI_BIAS, __half>,
                         cudaFuncAttributeMaxDynamicSharedMemorySize, SMEM_BYTES);
    cudaFuncSetAttribute((const void*)hmma_gemm_nt<EPI_EXP, __half>,
                         cudaFuncAttributeMaxDynamicSharedMemorySize, SMEM_BYTES);
    cudaFuncSetAttribute((const void*)hmma_gemm_nt<EPI_NONE, float>,
                         cudaFuncAttributeMaxDynamicSharedMemorySize, SMEM_BYTES);

    dim3 tb(32, 8);

    // 0) x -> fp16 ; bias concat ; merged weight transpose
    f2h_kernel<<<(BSZ * SEQ * EMB) / 4 / 256, 256>>>((const float4*)x, (__half2*)xr);
    bias_cat_kernel<<<EMB / 256, 256>>>(bq, bk, bv, bc);
    wtrans_kernel<<<dim3(EMB / 32, EMB / 32, 3), tb>>>(Wq, Wk, Wv, wt);

    // 1) merged projection (NT): qkv[8192,3072] = xr @ wt^T + bc
    dim3 gp(NQKV / BN, (BSZ * SEQ) / BM, 1);                 // (48, 64)
    hmma_gemm_nt<EPI_BIAS, __half><<<gp, 128, SMEM_BYTES>>>(
        xr, wt, bc, qkv, nullptr, EMB, EMB, EMB, NQKV, 1.f, 0, 0, 0);

    // 2) E = exp(Q K^T / 32) + fused per-m-tile column partial sums
    dim3 gs(SEQ / BN, SEQ / BM, BSZ);                        // (32, 16, 4)
    hmma_gemm_nt<EPI_EXP, __half><<<gs, 128, SMEM_BYTES>>>(
        qkv, qkv + EMB, nullptr, s, csp, EMB, NQKV, NQKV, SEQ, 1.f / 32.f,
        (size_t)SEQ * NQKV, (size_t)SEQ * NQKV, (size_t)SEQ * SEQ);

    // 3) Vt[e][k] = V[k][e] / colsum[k]   (combine fused inline)
    vt_kernel<<<dim3(EMB / 32, SEQ / 32, BSZ), tb>>>(qkv, vt, csp);

    // 4) out = E @ Vt^T (NT, fp32 out)
    dim3 go(EMB / BN, SEQ / BM, BSZ);                        // (16, 16, 4)
    hmma_gemm_nt<EPI_NONE, float><<<go, 128, SMEM_BYTES>>>(
        s, vt, nullptr, out, nullptr, SEQ, SEQ, SEQ, EMB, 1.f,
        (size_t)SEQ * SEQ, (size_t)EMB * SEQ, (size_t)SEQ * EMB);
}

// round 16
// speedup vs baseline: 1.1186x; 1.1186x over previous
#include <cuda_runtime.h>
#include <cuda_fp16.h>
#include <math.h>
#include <stdint.h>

#define BSZ 4
#define SEQ 2048
#define EMB 1024
#define NQKV 3072

// ---------------------------------------------------------------------------
// Scratch (__device__ globals: no allocations allowed)
// ---------------------------------------------------------------------------
__device__ __align__(16) __half g_xr [(size_t)BSZ * SEQ * EMB];     // x -> fp16
__device__ __align__(16) __half g_qkv[(size_t)BSZ * SEQ * NQKV];    // q|k|v interleaved
__device__ __align__(16) __half g_s  [(size_t)BSZ * SEQ * SEQ];     // E = exp(scores)
__device__ __align__(16) __half g_wt [3 * (size_t)EMB * EMB];       // W^T fp16 (q|k|v)
__device__ __align__(16) __half g_vt [(size_t)BSZ * EMB * SEQ];     // V^T / colsum
__device__ float g_csp[16 * (size_t)BSZ * SEQ];  // colsum partials (per m-tile)
__device__ float g_bc [NQKV];                    // concatenated bias

// ---------------------------------------------------------------------------
// Helpers
// ---------------------------------------------------------------------------
__device__ __forceinline__ uint32_t smem_u32(const void* p) {
    uint32_t a;
    asm("{ .reg .u64 t; cvta.to.shared.u64 t, %1; cvt.u32.u64 %0, t; }" : "=r"(a) : "l"(p));
    return a;
}
__device__ __forceinline__ void cpa16(uint32_t dst, const void* src) {
    asm volatile("cp.async.cg.shared.global [%0], [%1], 16;" :: "r"(dst), "l"(src));
}
#define CP_COMMIT() asm volatile("cp.async.commit_group;" ::: "memory")
#define CP_WAIT1()  asm volatile("cp.async.wait_group 1;" ::: "memory")

__device__ __forceinline__ void mma_f16(float* c,
    uint32_t a0, uint32_t a1, uint32_t a2, uint32_t a3, uint32_t b0, uint32_t b1)
{
    asm volatile("mma.sync.aligned.m16n8k16.row.col.f32.f16.f16.f32 "
        "{%0,%1,%2,%3}, {%4,%5,%6,%7}, {%8,%9}, {%0,%1,%2,%3};"
        : "+f"(c[0]), "+f"(c[1]), "+f"(c[2]), "+f"(c[3])
        : "r"(a0), "r"(a1), "r"(a2), "r"(a3), "r"(b0), "r"(b1));
}
__device__ __forceinline__ void ldsm_x4(uint32_t& r0, uint32_t& r1,
                                        uint32_t& r2, uint32_t& r3, uint32_t addr)
{
    asm volatile("ldmatrix.sync.aligned.m8n8.x4.shared.b16 {%0,%1,%2,%3}, [%4];"
        : "=r"(r0), "=r"(r1), "=r"(r2), "=r"(r3) : "r"(addr));
}

// ---------------------------------------------------------------------------
// fp16 mma.sync GEMM, NT: C[m][n] = epi(alpha * sum_k A[m][k]*B[n][k])
// 128x128x64 CTA tile (halves), 256 threads (8 warps of 64x32), 3-stage cp.async.
// Mainloop operand loads via ldmatrix.x4 (6 per chunk vs 24 scalar LDS).
// lda/ldb/ldc are row strides in elements; K is the contraction length.
// EPI_EXP also emits deterministic per-CTA column partial sums to csp.
// ---------------------------------------------------------------------------
#define BM 128
#define BN 128
#define BKH 64                        // halves per k-tile (128 bytes/row)
#define STAGES 3
#define PADW 36                       // b32 words per smem row (32 data + 4 pad)
#define ROW_BYTES (PADW * 4)          // 144
#define SMS_BYTES (BM * ROW_BYTES)    // per operand per stage (18432)
#define STAGE_BYTES (2 * SMS_BYTES)
#define SMEM_BYTES (STAGES * STAGE_BYTES)   // 110592

#define EPI_BIAS 0
#define EPI_EXP  1
#define EPI_NONE 2

template <int EPI, typename OutT>
__global__ void __launch_bounds__(256, 2) hmma_gemm_nt(
    const __half* __restrict__ A, const __half* __restrict__ B,
    const float* __restrict__ bias, OutT* __restrict__ C,
    float* __restrict__ csp,
    int K, int lda, int ldb, int ldc, float alpha,
    size_t sA, size_t sB, size_t sC)
{
    extern __shared__ char smem[];
    A += (size_t)blockIdx.z * sA;
    B += (size_t)blockIdx.z * sB;
    C += (size_t)blockIdx.z * sC;

    const int tid  = threadIdx.x;
    const int lane = tid & 31;
    const int wid  = tid >> 5;
    const int wm   = wid & 1;         // 2 m-slices of 64
    const int wn   = wid >> 1;        // 4 n-slices of 32
    const int bm = blockIdx.y * BM;
    const int bn = blockIdx.x * BN;

    const __half* Ab = A + (size_t)bm * lda;
    const __half* Bb = B + (size_t)bn * ldb;
    const uint32_t sb = smem_u32(smem);

    const int NT = K >> 6;            // k-tiles of 64 halves
    const int lr = tid >> 3;          // 0..31 base row
    const int lc = tid & 7;           // 16B chunk in 128B row

    // ldmatrix per-thread base offsets (within a stage)
    uint32_t a_off[4];
    #pragma unroll
    for (int mf = 0; mf < 4; mf++)
        a_off[mf] = (uint32_t)(wm * 64 + mf * 16 + (lane & 15)) * ROW_BYTES
                  + (uint32_t)(lane >> 4) * 16;
    uint32_t b_off[2];
    #pragma unroll
    for (int p = 0; p < 2; p++)
        b_off[p] = SMS_BYTES
                 + (uint32_t)(wn * 32 + p * 16 + (lane & 7) + ((lane >> 4) & 1) * 8) * ROW_BYTES
                 + (uint32_t)((lane >> 3) & 1) * 16;

    // prologue: stages 0..1
    #pragma unroll
    for (int st = 0; st < STAGES - 1; st++) {
        const int k0 = st * BKH;
        const uint32_t dA = sb + (uint32_t)st * STAGE_BYTES;
        const uint32_t dB = dA + SMS_BYTES;
        #pragma unroll
        for (int i = 0; i < 4; i++) {
            const int m = lr + 32 * i;
            const uint32_t so = (uint32_t)m * ROW_BYTES + lc * 16;
            cpa16(dA + so, Ab + (size_t)m * lda + k0 + lc * 8);
            cpa16(dB + so, Bb + (size_t)m * ldb + k0 + lc * 8);
        }
        CP_COMMIT();
    }

    float acc[64];
    #pragma unroll
    for (int i = 0; i < 64; i++) acc[i] = 0.0f;

    const int g  = lane >> 2;         // 0..7
    const int tg = lane & 3;          // 0..3

    for (int kt = 0; kt < NT; kt++) {
        CP_WAIT1();
        __syncthreads();

        if (kt + STAGES - 1 < NT) {
            const int st = (kt + STAGES - 1) % STAGES;
            const int k0 = (kt + STAGES - 1) * BKH;
            const uint32_t dA = sb + (uint32_t)st * STAGE_BYTES;
            const uint32_t dB = dA + SMS_BYTES;
            #pragma unroll
            for (int i = 0; i < 4; i++) {
                const int m = lr + 32 * i;
                const uint32_t so = (uint32_t)m * ROW_BYTES + lc * 16;
                cpa16(dA + so, Ab + (size_t)m * lda + k0 + lc * 8);
                cpa16(dB + so, Bb + (size_t)m * ldb + k0 + lc * 8);
            }
        }
        CP_COMMIT();

        const uint32_t stage = sb + (uint32_t)(kt % STAGES) * STAGE_BYTES;

        #pragma unroll
        for (int ch = 0; ch < 4; ch++) {          // 4 k16-chunks per tile
            const uint32_t cb = stage + ch * 32;  // 32B = 16 halves along k
            uint32_t a[4][4];
            #pragma unroll
            for (int mf = 0; mf < 4; mf++)
                ldsm_x4(a[mf][0], a[mf][1], a[mf][2], a[mf][3], cb + a_off[mf]);
            uint32_t b[2][4];
            #pragma unroll
            for (int p = 0; p < 2; p++)
                ldsm_x4(b[p][0], b[p][1], b[p][2], b[p][3], cb + b_off[p]);

            #pragma unroll
            for (int mf = 0; mf < 4; mf++) {
                #pragma unroll
                for (int nf = 0; nf < 4; nf++) {
                    const int p = nf >> 1, h = nf & 1;
                    mma_f16(&acc[(mf * 4 + nf) * 4],
                            a[mf][0], a[mf][1], a[mf][2], a[mf][3],
                            b[p][h * 2 + 0], b[p][h * 2 + 1]);
                }
            }
        }
    }

    // ---------------- Epilogue ----------------
    float psum[4][2];
    if (EPI == EPI_EXP) {
        #pragma unroll
        for (int nf = 0; nf < 4; nf++) { psum[nf][0] = 0.f; psum[nf][1] = 0.f; }
    }

    const int cc = tg * 2;
    #pragma unroll
    for (int mf = 0; mf < 4; mf++) {
        #pragma unroll
        for (int rh = 0; rh < 2; rh++) {
            const int row = bm + wm * 64 + mf * 16 + rh * 8 + g;
            OutT* crow = C + (size_t)row * ldc + bn + wn * 32;
            #pragma unroll
            for (int nf = 0; nf < 4; nf++) {
                float v0 = acc[(mf * 4 + nf) * 4 + rh * 2 + 0];
                float v1 = acc[(mf * 4 + nf) * 4 + rh * 2 + 1];
                const int col = nf * 8 + cc;
                if (EPI == EPI_BIAS) {
                    const __half h0 = __float2half_rn(v0 + bias[bn + wn * 32 + col + 0]);
                    const __half h1 = __float2half_rn(v1 + bias[bn + wn * 32 + col + 1]);
                    *(__half2*)((__half*)crow + col) = __halves2half2(h0, h1);
                } else if (EPI == EPI_EXP) {
                    const __half h0 = __float2half_rn(__expf(v0 * alpha));
                    const __half h1 = __float2half_rn(__expf(v1 * alpha));
                    psum[nf][0] += __half2float(h0);   // sum the EXACT stored values
                    psum[nf][1] += __half2float(h1);
                    *(__half2*)((__half*)crow + col) = __halves2half2(h0, h1);
                } else {
                    *(float2*)((float*)crow + col) = make_float2(v0, v1);
                }
            }
        }
    }

    if (EPI == EPI_EXP) {
        // reduce over g (lanes xor 4,8,16 share the same column pair)
        #pragma unroll
        for (int nf = 0; nf < 4; nf++) {
            #pragma unroll
            for (int h = 0; h < 2; h++) {
                float v = psum[nf][h];
                v += __shfl_xor_sync(0xffffffffu, v, 4);
                v += __shfl_xor_sync(0xffffffffu, v, 8);
                v += __shfl_xor_sync(0xffffffffu, v, 16);
                psum[nf][h] = v;
            }
        }
        __syncthreads();                      // mainloop smem reads done
        float* csum = (float*)smem;           // reuse: [2][128]
        if (g == 0) {
            #pragma unroll
            for (int nf = 0; nf < 4; nf++) {
                csum[wm * 128 + wn * 32 + nf * 8 + cc + 0] = psum[nf][0];
                csum[wm * 128 + wn * 32 + nf * 8 + cc + 1] = psum[nf][1];
            }
        }
        __syncthreads();
        if (tid < 128) {
            const float t = csum[tid] + csum[128 + tid];
            csp[(size_t)blockIdx.y * BSZ * SEQ + (size_t)blockIdx.z * SEQ + bn + tid] = t;
        }
    }
}

// ---------------------------------------------------------------------------
// x -> fp16 copy
// ---------------------------------------------------------------------------
__global__ void f2h_kernel(const float4* __restrict__ in, __half2* __restrict__ out)
{
    const size_t i = (size_t)blockIdx.x * blockDim.x + threadIdx.x;
    const float4 v = in[i];
    out[2 * i + 0] = __floats2half2_rn(v.x, v.y);
    out[2 * i + 1] = __floats2half2_rn(v.z, v.w);
}

// ---------------------------------------------------------------------------
// Merged weight transpose + bias concat (grid.z selects W):
//   wt[z][n][k] = (half)W_z[k][n];   block (0,0,z) also copies bias_z -> bc
// ---------------------------------------------------------------------------
__global__ void wtrans_kernel(const float* __restrict__ W0, const float* __restrict__ W1,
                              const float* __restrict__ W2, __half* __restrict__ wt,
                              const float* __restrict__ b0, const float* __restrict__ b1,
                              const float* __restrict__ b2, float* __restrict__ bc)
{
    __shared__ float t[32][33];
    const int z = blockIdx.z;
    const float* in = (z == 0) ? W0 : (z == 1) ? W1 : W2;
    __half* out = wt + (size_t)z * EMB * EMB;
    const int r0 = blockIdx.y * 32, c0 = blockIdx.x * 32;
    const int tid = threadIdx.y * 32 + threadIdx.x;

    if (blockIdx.x == 0 && blockIdx.y == 0) {
        const float* bsrc = (z == 0) ? b0 : (z == 1) ? b1 : b2;
        #pragma unroll
        for (int i = tid; i < EMB; i += 256)
            bc[z * EMB + i] = bsrc[i];
    }

    #pragma unroll
    for (int i = threadIdx.y; i < 32; i += 8)
        t[i][threadIdx.x] = in[(size_t)(r0 + i) * EMB + c0 + threadIdx.x];
    __syncthreads();
    #pragma unroll
    for (int i = threadIdx.y; i < 32; i += 8)
        out[(size_t)(c0 + i) * EMB + r0 + threadIdx.x] = __float2half_rn(t[threadIdx.x][i]);
}

// ---------------------------------------------------------------------------
// Vt build with inline colsum combine:
//   cs[k] = sum_{c<16} csp[c][b][k]   (same order as before -> deterministic)
//   vt[e][k] = (half)( v[k][e] / cs[k] )      v = qkv column block 2048..3071
// ---------------------------------------------------------------------------
__global__ void vt_kernel(const __half* __restrict__ qkv, __half* __restrict__ vt,
                          const float* __restrict__ csp)
{
    __shared__ float t[32][33];
    __shared__ float inv[32];
    const int b = blockIdx.z;
    const __half* v = qkv + (size_t)b * SEQ * NQKV + 2 * EMB;
    __half* vo = vt + (size_t)b * EMB * SEQ;
    const int r0 = blockIdx.y * 32;   // k rows
    const int c0 = blockIdx.x * 32;   // e cols
    const int tid = threadIdx.y * 32 + threadIdx.x;

    if (tid < 32) {
        float s = 0.f;
        #pragma unroll
        for (int c = 0; c < 16; c++)
            s += csp[(size_t)c * BSZ * SEQ + (size_t)b * SEQ + r0 + tid];
        inv[tid] = __fdividef(1.0f, s);
    }
    __syncthreads();

    #pragma unroll
    for (int i = threadIdx.y; i < 32; i += 8)
        t[i][threadIdx.x] = __half2float(v[(size_t)(r0 + i) * NQKV + c0 + threadIdx.x]) * inv[i];
    __syncthreads();
    #pragma unroll
    for (int i = threadIdx.y; i < 32; i += 8)
        vo[(size_t)(c0 + i) * SEQ + r0 + threadIdx.x] = __float2half_rn(t[threadIdx.x][i]);
}

// ---------------------------------------------------------------------------
// Launch
// ---------------------------------------------------------------------------
extern "C" void kernel_launch(void* const* d_in, const int* in_sizes, int n_in,
                              void* d_out, int out_size)
{
    const float* x  = (const float*)d_in[0];
    const float* Wq = (const float*)d_in[1];
    const float* bq = (const float*)d_in[2];
    const float* Wk = (const float*)d_in[3];
    const float* bk = (const float*)d_in[4];
    const float* Wv = (const float*)d_in[5];
    const float* bv = (const float*)d_in[6];
    float* out = (float*)d_out;

    __half *xr, *qkv, *s, *wt, *vt;
    float *csp, *bc;
    cudaGetSymbolAddress((void**)&xr,  g_xr);
    cudaGetSymbolAddress((void**)&qkv, g_qkv);
    cudaGetSymbolAddress((void**)&s,   g_s);
    cudaGetSymbolAddress((void**)&wt,  g_wt);
    cudaGetSymbolAddress((void**)&vt,  g_vt);
    cudaGetSymbolAddress((void**)&csp, g_csp);
    cudaGetSymbolAddress((void**)&bc,  g_bc);

    cudaFuncSetAttribute((const void*)hmma_gemm_nt<EPI_BIAS, __half>,
                         cudaFuncAttributeMaxDynamicSharedMemorySize, SMEM_BYTES);
    cudaFuncSetAttribute((const void*)hmma_gemm_nt<EPI_EXP, __half>,
                         cudaFuncAttributeMaxDynamicSharedMemorySize, SMEM_BYTES);
    cudaFuncSetAttribute((const void*)hmma_gemm_nt<EPI_NONE, float>,
                         cudaFuncAttributeMaxDynamicSharedMemorySize, SMEM_BYTES);

    dim3 tb(32, 8);

    // 0) x -> fp16 ; merged weight transpose + bias concat
    f2h_kernel<<<(BSZ * SEQ * EMB) / 4 / 256, 256>>>((const float4*)x, (__half2*)xr);
    wtrans_kernel<<<dim3(EMB / 32, EMB / 32, 3), tb>>>(Wq, Wk, Wv, wt, bq, bk, bv, bc);

    // 1) merged projection (NT): qkv[8192,3072] = xr @ wt^T + bc
    dim3 gp(NQKV / BN, (BSZ * SEQ) / BM, 1);
    hmma_gemm_nt<EPI_BIAS, __half><<<gp, 256, SMEM_BYTES>>>(
        xr, wt, bc, qkv, nullptr, EMB, EMB, EMB, NQKV, 1.f, 0, 0, 0);

    // 2) E = exp(Q K^T / 32) + fused per-m-tile column partial sums
    dim3 gs(SEQ / BN, SEQ / BM, BSZ);   // (16, 16, 4)
    hmma_gemm_nt<EPI_EXP, __half><<<gs, 256, SMEM_BYTES>>>(
        qkv, qkv + EMB, nullptr, s, csp, EMB, NQKV, NQKV, SEQ, 1.f / 32.f,
        (size_t)SEQ * NQKV, (size_t)SEQ * NQKV, (size_t)SEQ * SEQ);

    // 3) Vt[e][k] = V[k][e] / colsum[k]   (combine fused inline)
    vt_kernel<<<dim3(EMB / 32, SEQ / 32, BSZ), tb>>>(qkv, vt, csp);

    // 4) out = E @ Vt^T (NT, fp32 out)
    dim3 go(EMB / BN, SEQ / BM, BSZ);
    hmma_gemm_nt<EPI_NONE, float><<<go, 256, SMEM_BYTES>>>(
        s, vt, nullptr, out, nullptr, SEQ, SEQ, SEQ, EMB, 1.f,
        (size_t)SEQ * SEQ, (size_t)EMB * SEQ, (size_t)SEQ * EMB);
}